// round 3
// baseline (speedup 1.0000x reference)
#include <cuda_runtime.h>
#include <math.h>

// Problem constants
#define BATCH 8
#define NC    16
#define HH    320
#define WW    320
#define HW    102400
#define NITER 10
#define RED_BLKS 400

// ---------------- scratch (device globals; no runtime allocation) ----------------
__device__ float2 g_k[BATCH * NC * HW];   // coil k-space buffer (permuted freq layout)
__device__ float2 g_x[BATCH * HW];
__device__ float2 g_r[BATCH * HW];
__device__ float2 g_pA[BATCH * HW];
__device__ float2 g_pB[BATCH * HW];
__device__ float2 g_Ap[BATCH * HW];
__device__ float  g_maskP[BATCH * HW];        // permuted + scaled mask
__device__ float  g_partPA[BATCH * HH];       // p.Ap partials (from inv_combine)
__device__ float  g_partRR[BATCH * RED_BLKS]; // r.r partials (from update_xr / init)
__device__ float  g_rTrArr[(NITER + 1) * BATCH];
__device__ float2 g_tw320[288];               // exp(-2pi i k*lane/320), k=1..9
__device__ float2 g_tw32[128];                // fft32 stage twiddles, s=0..3 (m=16,8,4,2)

// ---------------- complex helpers ----------------
__device__ __forceinline__ float2 cmul(float2 a, float2 b) {
    return make_float2(a.x*b.x - a.y*b.y, a.x*b.y + a.y*b.x);
}
__device__ __forceinline__ float2 cmulconj(float2 c, float2 v) { // conj(c)*v
    return make_float2(c.x*v.x + c.y*v.y, c.x*v.y - c.y*v.x);
}
__device__ __forceinline__ float2 cadd(float2 a, float2 b) { return make_float2(a.x+b.x, a.y+b.y); }
__device__ __forceinline__ float2 csub(float2 a, float2 b) { return make_float2(a.x-b.x, a.y-b.y); }
__device__ __forceinline__ int br5(int l) { return (int)(__brev((unsigned)l) >> 27); }

// ---------------- radix-5 ----------------
#define C51 0.30901699437494745f
#define C52 (-0.8090169943749475f)
#define S51 0.9510565162951535f
#define S52 0.5877852522924731f

template<int DIR>
__device__ __forceinline__ void fft5(float2 a0, float2 a1, float2 a2, float2 a3, float2 a4,
                                     float2& b0, float2& b1, float2& b2, float2& b3, float2& b4) {
    const float dir = (float)DIR;
    float2 t1 = cadd(a1, a4), t2 = cadd(a2, a3);
    float2 t3 = csub(a1, a4), t4 = csub(a2, a3);
    float2 m1 = make_float2(a0.x + C51*t1.x + C52*t2.x, a0.y + C51*t1.y + C52*t2.y);
    float2 m2 = make_float2(a0.x + C52*t1.x + C51*t2.x, a0.y + C52*t1.y + C51*t2.y);
    float2 u1 = make_float2(S51*t3.x + S52*t4.x, S51*t3.y + S52*t4.y);
    float2 u2 = make_float2(S52*t3.x - S51*t4.x, S52*t3.y - S51*t4.y);
    b0 = make_float2(a0.x + t1.x + t2.x, a0.y + t1.y + t2.y);
    b1 = make_float2(m1.x - dir*u1.y, m1.y + dir*u1.x);
    b4 = make_float2(m1.x + dir*u1.y, m1.y - dir*u1.x);
    b2 = make_float2(m2.x - dir*u2.y, m2.y + dir*u2.x);
    b3 = make_float2(m2.x + dir*u2.y, m2.y - dir*u2.x);
}

// ---------------- per-lane 10-point FFT ----------------
template<int DIR>
__device__ __forceinline__ void fft10(float2 v[10]) {
    const float dir = (float)DIR;
    float2 e0,e1,e2,e3,e4, o0,o1,o2,o3,o4;
    fft5<DIR>(v[0], v[2], v[4], v[6], v[8], e0, e1, e2, e3, e4);
    fft5<DIR>(v[1], v[3], v[5], v[7], v[9], o0, o1, o2, o3, o4);
    const float c1 = 0.80901699437494745f, s1 = 0.58778525229247314f;
    const float c2 = 0.30901699437494745f, s2 = 0.95105651629515357f;
    float2 t;
    v[0] = cadd(e0, o0);                       v[5] = csub(e0, o0);
    t = cmul(o1, make_float2( c1, dir*s1));    v[1] = cadd(e1, t); v[6] = csub(e1, t);
    t = cmul(o2, make_float2( c2, dir*s2));    v[2] = cadd(e2, t); v[7] = csub(e2, t);
    t = cmul(o3, make_float2(-c2, dir*s2));    v[3] = cadd(e3, t); v[8] = csub(e3, t);
    t = cmul(o4, make_float2(-c1, dir*s1));    v[4] = cadd(e4, t); v[9] = csub(e4, t);
}

// ---------------- full 320-pt forward: v[j]=x[lane+32j] -> lane holds X[10*br5(lane)+j] ----------------
__device__ __forceinline__ void fft320_fwd(float2 v[10], int lane) {
    fft10<-1>(v);
    #pragma unroll
    for (int k = 1; k < 10; k++) v[k] = cmul(v[k], g_tw320[(k-1)*32 + lane]);
    #pragma unroll
    for (int s = 0; s < 4; s++) {
        int m = 16 >> s;
        float2 w = g_tw32[s*32 + lane];
        bool up = (lane & m) != 0;
        #pragma unroll
        for (int r = 0; r < 10; r++) {
            float ox = __shfl_xor_sync(0xffffffffu, v[r].x, m);
            float oy = __shfl_xor_sync(0xffffffffu, v[r].y, m);
            v[r] = up ? cmul(make_float2(ox - v[r].x, oy - v[r].y), w)
                      : make_float2(v[r].x + ox, v[r].y + oy);
        }
    }
    bool up = (lane & 1) != 0;   // m=1: no twiddle
    #pragma unroll
    for (int r = 0; r < 10; r++) {
        float ox = __shfl_xor_sync(0xffffffffu, v[r].x, 1);
        float oy = __shfl_xor_sync(0xffffffffu, v[r].y, 1);
        v[r] = up ? make_float2(ox - v[r].x, oy - v[r].y)
                  : make_float2(v[r].x + ox, v[r].y + oy);
    }
}

// ---------------- full 320-pt inverse (unnormalized) ----------------
__device__ __forceinline__ void fft320_inv(float2 v[10], int lane) {
    bool up1 = (lane & 1) != 0;  // m=1: no twiddle
    #pragma unroll
    for (int r = 0; r < 10; r++) {
        float ox = __shfl_xor_sync(0xffffffffu, v[r].x, 1);
        float oy = __shfl_xor_sync(0xffffffffu, v[r].y, 1);
        v[r] = up1 ? make_float2(ox - v[r].x, oy - v[r].y)
                   : make_float2(v[r].x + ox, v[r].y + oy);
    }
    #pragma unroll
    for (int s = 3; s >= 0; s--) {
        int m = 16 >> s;
        float2 wf = g_tw32[s*32 + lane];
        float2 w = make_float2(wf.x, -wf.y);
        bool up = (lane & m) != 0;
        #pragma unroll
        for (int r = 0; r < 10; r++) {
            float2 t = up ? cmul(v[r], w) : v[r];
            float ox = __shfl_xor_sync(0xffffffffu, t.x, m);
            float oy = __shfl_xor_sync(0xffffffffu, t.y, m);
            v[r] = up ? make_float2(ox - t.x, oy - t.y)
                      : make_float2(t.x + ox, t.y + oy);
        }
    }
    #pragma unroll
    for (int k = 1; k < 10; k++) {
        float2 wf = g_tw320[(k-1)*32 + lane];
        v[k] = cmul(v[k], make_float2(wf.x, -wf.y));
    }
    fft10<+1>(v);
}

// ---------------- reductions ----------------
__device__ __forceinline__ float block_reduce_256(float v) {
    __shared__ float red[256];
    red[threadIdx.x] = v;
    __syncthreads();
    #pragma unroll
    for (int s = 128; s > 0; s >>= 1) {
        if (threadIdx.x < s) red[threadIdx.x] += red[threadIdx.x + s];
        __syncthreads();
    }
    return red[0];
}
__device__ __forceinline__ float warp_reduce(float v) {
    #pragma unroll
    for (int o = 16; o > 0; o >>= 1) v += __shfl_xor_sync(0xffffffffu, v, o);
    return v;
}

// ---------------- twiddle table init (one-time per call, exact) ----------------
__global__ void __launch_bounds__(256) k_twinit() {
    int t = blockIdx.x * 256 + threadIdx.x;
    if (t < 288) {
        int k = t / 32 + 1, l = t & 31;
        double a = -2.0 * M_PI * (double)(k * l) / 320.0;
        double s, c; sincos(a, &s, &c);
        g_tw320[t] = make_float2((float)c, (float)s);
    } else if (t < 416) {
        int u = t - 288;
        int s2 = u >> 5, l = u & 31;
        int m = 16 >> s2;
        int j = l & (m - 1);
        double a = -M_PI * (double)j / (double)m;
        double ss, cc; sincos(a, &ss, &cc);
        g_tw32[u] = make_float2((float)cc, (float)ss);
    }
}

// ---------------- mask prep: permuted + scaled ----------------
__global__ void __launch_bounds__(256) k_maskprep(const int* __restrict__ mask) {
    int e = blockIdx.x * 256 + threadIdx.x;      // [0, B*HW)
    int b = e / HW; int rem = e - b * HW;
    int w_mem = rem / 320; int idx = rem - w_mem * 320;
    int l = idx & 31, j = idx >> 5;
    int hfreq = 10 * br5(l) + j;
    int wfreq = 10 * br5(w_mem & 31) + (w_mem >> 5);
    g_maskP[e] = (float)mask[b * HW + hfreq * 320 + wfreq] * (1.0f / 102400.0f);
}

// ---------------- K1: (optional p-update) ; coil = csm*p ; forward row FFT ----------------
__global__ void __launch_bounds__(256) k_rows_fwd(const float* __restrict__ csm,
                                                  int it, int prd, int pwr, int upd) {
    int warp = threadIdx.x >> 5, lane = threadIdx.x & 31;
    int row = blockIdx.x * 8 + warp;          // bc*320 + h  (blocks never straddle coils)
    int bc = row / 320, h = row - bc * 320;
    int b = bc >> 4, coil = bc & 15;
    const float2* pr = prd ? g_pB : g_pA;
    float2* pw = pwr ? g_pB : g_pA;
    int base = b * HW + h * WW;

    float be = 0.f;
    if (upd) {
        float s = 0.f;
        for (int t = lane; t < RED_BLKS; t += 32) s += g_partRR[b * RED_BLKS + t];
        s = warp_reduce(s);                           // rTr_new, identical in all blocks
        float rold = g_rTrArr[(it - 1) * BATCH + b];
        be = s / rold;
        if (lane == 0) g_rTrArr[it * BATCH + b] = s;  // duplicate same-value writes: benign
    }

    const float2* crow = (const float2*)csm + bc * HW + h * WW;
    float2 v[10];
    #pragma unroll
    for (int j = 0; j < 10; j++) {
        int idx = lane + 32 * j;
        float2 pv;
        if (upd) {
            float2 rv = g_r[base + idx];
            float2 po = pr[base + idx];
            pv = make_float2(rv.x + be * po.x, rv.y + be * po.y);
            if (coil == 0) pw[base + idx] = pv;
        } else {
            pv = pr[base + idx];
        }
        v[j] = cmul(crow[idx], pv);
    }
    fft320_fwd(v, lane);
    float2* out = g_k + bc * HW + h * WW;
    #pragma unroll
    for (int j = 0; j < 10; j++) out[lane + 32 * j] = v[j];   // permuted-freq layout
}

// ---------------- K2: column FFT + mask + column IFFT ----------------
__global__ void __launch_bounds__(256) k_cols() {
    __shared__ float sRe[8][324];
    __shared__ float sIm[8][324];
    int bc = blockIdx.x / 40;
    int w0 = (blockIdx.x - bc * 40) * 8;
    int b = bc >> 4;
    float2* base = g_k + bc * HW;

    for (int idx = threadIdx.x; idx < 320 * 8; idx += 256) {
        int h = idx >> 3, c = idx & 7;
        float2 t = base[h * WW + w0 + c];
        sRe[c][h] = t.x; sIm[c][h] = t.y;
    }
    __syncthreads();

    int warp = threadIdx.x >> 5, lane = threadIdx.x & 31;
    float2 v[10];
    #pragma unroll
    for (int j = 0; j < 10; j++) {
        int h = lane + 32 * j;
        v[j] = make_float2(sRe[warp][h], sIm[warp][h]);
    }
    fft320_fwd(v, lane);

    const float* mrow = g_maskP + b * HW + (w0 + warp) * 320;
    #pragma unroll
    for (int j = 0; j < 10; j++) {
        float m = mrow[lane + 32 * j];
        v[j].x *= m; v[j].y *= m;
    }
    fft320_inv(v, lane);

    #pragma unroll
    for (int j = 0; j < 10; j++) {
        int h = lane + 32 * j;
        sRe[warp][h] = v[j].x; sIm[warp][h] = v[j].y;
    }
    __syncthreads();
    for (int idx = threadIdx.x; idx < 320 * 8; idx += 256) {
        int h = idx >> 3, c = idx & 7;
        base[h * WW + w0 + c] = make_float2(sRe[c][h], sIm[c][h]);
    }
}

// ---------------- K3: inverse row FFT + conj(csm) + combine + lam*p + p.Ap partial ----------------
__global__ void __launch_bounds__(256) k_inv_combine(const float* __restrict__ csm,
                                                     const float* __restrict__ lam, int pwr) {
    __shared__ float2 sAcc[8][320];
    int warp = threadIdx.x >> 5, lane = threadIdx.x & 31;
    int b = blockIdx.x / 320, h = blockIdx.x - b * 320;
    const float2* pbuf = pwr ? g_pB : g_pA;

    float2 acc[10];
    #pragma unroll
    for (int j = 0; j < 10; j++) acc[j] = make_float2(0.f, 0.f);

    #pragma unroll
    for (int cc = 0; cc < 2; cc++) {
        int bc = b * 16 + warp + 8 * cc;
        const float2* krow = g_k + bc * HW + h * WW;
        float2 v[10];
        #pragma unroll
        for (int j = 0; j < 10; j++) v[j] = krow[lane + 32 * j];
        fft320_inv(v, lane);
        const float2* crow = (const float2*)csm + bc * HW + h * WW;
        #pragma unroll
        for (int j = 0; j < 10; j++) {
            float2 cv = crow[lane + 32 * j];
            float2 t = cmulconj(cv, v[j]);
            acc[j].x += t.x; acc[j].y += t.y;
        }
    }
    #pragma unroll
    for (int j = 0; j < 10; j++) sAcc[warp][lane + 32 * j] = acc[j];
    __syncthreads();

    const float2* prow = pbuf + b * HW + h * WW;
    float2* aprow = g_Ap + b * HW + h * WW;
    float l0 = lam[0];
    float dot = 0.f;
    for (int e = threadIdx.x; e < 320; e += 256) {
        float2 s = make_float2(0.f, 0.f);
        #pragma unroll
        for (int w = 0; w < 8; w++) { s.x += sAcc[w][e].x; s.y += sAcc[w][e].y; }
        float2 pv = prow[e];
        float2 ap = make_float2(s.x + l0 * pv.x, s.y + l0 * pv.y);
        aprow[e] = ap;
        dot += pv.x * ap.x + pv.y * ap.y;
    }
    float tot = block_reduce_256(dot);
    if (threadIdx.x == 0) g_partPA[blockIdx.x] = tot;   // index = b*320 + h
}

// ---------------- K4: alpha (local reduce) ; x += a p ; r -= a Ap ; rr partial ----------------
__global__ void __launch_bounds__(256) k_update_xr(int it, int pwr) {
    int b = blockIdx.x / RED_BLKS;
    int idx = (blockIdx.x - b * RED_BLKS) * 256 + threadIdx.x;
    int e = b * HW + idx;
    int lane = threadIdx.x & 31;
    const float2* pbuf = pwr ? g_pB : g_pA;

    float s = 0.f;
    for (int t = lane; t < HH; t += 32) s += g_partPA[b * HH + t];
    s = warp_reduce(s);
    float a = g_rTrArr[it * BATCH + b] / s;

    float2 pv = pbuf[e], ap = g_Ap[e];
    float2 xv = g_x[e];
    xv.x += a * pv.x; xv.y += a * pv.y;
    g_x[e] = xv;
    float2 rv = g_r[e];
    rv.x -= a * ap.x; rv.y -= a * ap.y;
    g_r[e] = rv;
    float rr = rv.x * rv.x + rv.y * rv.y;
    float tot = block_reduce_256(rr);
    if (threadIdx.x == 0) g_partRR[blockIdx.x] = tot;
}

// ---------------- init: p=r=rhs, x=0, rr partials ----------------
__global__ void __launch_bounds__(256) k_init(const float* __restrict__ rhs) {
    int b = blockIdx.x / RED_BLKS;
    int idx = (blockIdx.x - b * RED_BLKS) * 256 + threadIdx.x;
    int e = b * HW + idx;
    float re = rhs[(b * 2 + 0) * HW + idx];
    float im = rhs[(b * 2 + 1) * HW + idx];
    float2 v = make_float2(re, im);
    g_pA[e] = v;
    g_r[e] = v;
    g_x[e] = make_float2(0.f, 0.f);
    float rr = re * re + im * im;
    float tot = block_reduce_256(rr);
    if (threadIdx.x == 0) g_partRR[blockIdx.x] = tot;
}

__global__ void __launch_bounds__(256) k_init_red() {
    int b = blockIdx.x;
    float v = 0.f;
    for (int t = threadIdx.x; t < RED_BLKS; t += 256) v += g_partRR[b * RED_BLKS + t];
    float tot = block_reduce_256(v);
    if (threadIdx.x == 0) g_rTrArr[b] = tot;   // it = 0
}

// ---------------- output: [B,H,W,2] ----------------
__global__ void __launch_bounds__(256) k_out(float* __restrict__ out) {
    int e = blockIdx.x * 256 + threadIdx.x;
    ((float2*)out)[e] = g_x[e];
}

// ---------------- launch ----------------
extern "C" void kernel_launch(void* const* d_in, const int* in_sizes, int n_in,
                              void* d_out, int out_size) {
    const float* rhs  = (const float*)d_in[0];
    const float* csm  = (const float*)d_in[1];
    const int*   mask = (const int*)d_in[2];
    const float* lam  = (const float*)d_in[3];
    float* out = (float*)d_out;

    const int EG = BATCH * RED_BLKS;      // 3200
    const int FG = BATCH * NC * HH / 8;   // 5120
    const int CG = BATCH * NC * (WW / 8); // 5120
    const int IG = BATCH * HH;            // 2560

    k_twinit<<<2, 256>>>();
    k_maskprep<<<EG, 256>>>(mask);
    k_init<<<EG, 256>>>(rhs);
    k_init_red<<<BATCH, 256>>>();

    for (int it = 0; it < NITER; it++) {
        int cur  = (it == 0) ? 0 : (it & 1);          // 0 = A, 1 = B
        int prev = (it == 0) ? 0 : ((it - 1) == 0 ? 0 : ((it - 1) & 1));
        int upd  = (it > 0) ? 1 : 0;
        k_rows_fwd<<<FG, 256>>>(csm, it, prev, cur, upd);
        k_cols<<<CG, 256>>>();
        k_inv_combine<<<IG, 256>>>(csm, lam, cur);
        k_update_xr<<<EG, 256>>>(it, cur);
    }

    k_out<<<EG, 256>>>(out);
}

// round 4
// speedup vs baseline: 1.2290x; 1.2290x over previous
#include <cuda_runtime.h>
#include <math.h>

// Problem constants
#define BATCH 8
#define NC    16
#define HH    320
#define WW    320
#define HW    102400
#define NITER 10
#define RED_BLKS 400

// ---------------- scratch (device globals; no runtime allocation) ----------------
__device__ float2 g_k[BATCH * NC * HW];   // coil k-space buffer (permuted freq layout)
__device__ float2 g_x[BATCH * HW];
__device__ float2 g_r[BATCH * HW];
__device__ float2 g_p[BATCH * HW];
__device__ float2 g_Ap[BATCH * HW];
__device__ float  g_maskP[BATCH * HW];    // permuted + scaled mask
__device__ float  g_part[BATCH * RED_BLKS];
__device__ float  g_rTr[BATCH];
__device__ float  g_alpha[BATCH];
__device__ float  g_beta[BATCH];
__device__ float2 g_tw320[288];           // exp(-2pi i k*lane/320), k=1..9
__device__ float2 g_tw32[128];            // fft32 stage twiddles, s=0..3 (m=16,8,4,2)

// ---------------- complex helpers ----------------
__device__ __forceinline__ float2 cmul(float2 a, float2 b) {
    return make_float2(a.x*b.x - a.y*b.y, a.x*b.y + a.y*b.x);
}
__device__ __forceinline__ float2 cmulconj(float2 c, float2 v) { // conj(c)*v
    return make_float2(c.x*v.x + c.y*v.y, c.x*v.y - c.y*v.x);
}
__device__ __forceinline__ float2 cadd(float2 a, float2 b) { return make_float2(a.x+b.x, a.y+b.y); }
__device__ __forceinline__ float2 csub(float2 a, float2 b) { return make_float2(a.x-b.x, a.y-b.y); }
__device__ __forceinline__ int br5(int l) { return (int)(__brev((unsigned)l) >> 27); }

// ---------------- radix-5 ----------------
#define C51 0.30901699437494745f
#define C52 (-0.8090169943749475f)
#define S51 0.9510565162951535f
#define S52 0.5877852522924731f

template<int DIR>
__device__ __forceinline__ void fft5(float2 a0, float2 a1, float2 a2, float2 a3, float2 a4,
                                     float2& b0, float2& b1, float2& b2, float2& b3, float2& b4) {
    const float dir = (float)DIR;
    float2 t1 = cadd(a1, a4), t2 = cadd(a2, a3);
    float2 t3 = csub(a1, a4), t4 = csub(a2, a3);
    float2 m1 = make_float2(a0.x + C51*t1.x + C52*t2.x, a0.y + C51*t1.y + C52*t2.y);
    float2 m2 = make_float2(a0.x + C52*t1.x + C51*t2.x, a0.y + C52*t1.y + C51*t2.y);
    float2 u1 = make_float2(S51*t3.x + S52*t4.x, S51*t3.y + S52*t4.y);
    float2 u2 = make_float2(S52*t3.x - S51*t4.x, S52*t3.y - S51*t4.y);
    b0 = make_float2(a0.x + t1.x + t2.x, a0.y + t1.y + t2.y);
    b1 = make_float2(m1.x - dir*u1.y, m1.y + dir*u1.x);
    b4 = make_float2(m1.x + dir*u1.y, m1.y - dir*u1.x);
    b2 = make_float2(m2.x - dir*u2.y, m2.y + dir*u2.x);
    b3 = make_float2(m2.x + dir*u2.y, m2.y - dir*u2.x);
}

// ---------------- per-lane 10-point FFT ----------------
template<int DIR>
__device__ __forceinline__ void fft10(float2 v[10]) {
    const float dir = (float)DIR;
    float2 e0,e1,e2,e3,e4, o0,o1,o2,o3,o4;
    fft5<DIR>(v[0], v[2], v[4], v[6], v[8], e0, e1, e2, e3, e4);
    fft5<DIR>(v[1], v[3], v[5], v[7], v[9], o0, o1, o2, o3, o4);
    const float c1 = 0.80901699437494745f, s1 = 0.58778525229247314f;
    const float c2 = 0.30901699437494745f, s2 = 0.95105651629515357f;
    float2 t;
    v[0] = cadd(e0, o0);                       v[5] = csub(e0, o0);
    t = cmul(o1, make_float2( c1, dir*s1));    v[1] = cadd(e1, t); v[6] = csub(e1, t);
    t = cmul(o2, make_float2( c2, dir*s2));    v[2] = cadd(e2, t); v[7] = csub(e2, t);
    t = cmul(o3, make_float2(-c2, dir*s2));    v[3] = cadd(e3, t); v[8] = csub(e3, t);
    t = cmul(o4, make_float2(-c1, dir*s1));    v[4] = cadd(e4, t); v[9] = csub(e4, t);
}

// ---------------- full 320-pt forward: v[j]=x[lane+32j] -> lane holds X[10*br5(lane)+j] ----------------
__device__ __forceinline__ void fft320_fwd(float2 v[10], int lane) {
    fft10<-1>(v);
    #pragma unroll
    for (int k = 1; k < 10; k++) v[k] = cmul(v[k], g_tw320[(k-1)*32 + lane]);
    #pragma unroll
    for (int s = 0; s < 4; s++) {
        int m = 16 >> s;
        float2 w = g_tw32[s*32 + lane];
        bool up = (lane & m) != 0;
        #pragma unroll
        for (int r = 0; r < 10; r++) {
            float ox = __shfl_xor_sync(0xffffffffu, v[r].x, m);
            float oy = __shfl_xor_sync(0xffffffffu, v[r].y, m);
            v[r] = up ? cmul(make_float2(ox - v[r].x, oy - v[r].y), w)
                      : make_float2(v[r].x + ox, v[r].y + oy);
        }
    }
    bool up = (lane & 1) != 0;   // m=1: no twiddle
    #pragma unroll
    for (int r = 0; r < 10; r++) {
        float ox = __shfl_xor_sync(0xffffffffu, v[r].x, 1);
        float oy = __shfl_xor_sync(0xffffffffu, v[r].y, 1);
        v[r] = up ? make_float2(ox - v[r].x, oy - v[r].y)
                  : make_float2(v[r].x + ox, v[r].y + oy);
    }
}

// ---------------- full 320-pt inverse (unnormalized) ----------------
__device__ __forceinline__ void fft320_inv(float2 v[10], int lane) {
    bool up1 = (lane & 1) != 0;  // m=1: no twiddle
    #pragma unroll
    for (int r = 0; r < 10; r++) {
        float ox = __shfl_xor_sync(0xffffffffu, v[r].x, 1);
        float oy = __shfl_xor_sync(0xffffffffu, v[r].y, 1);
        v[r] = up1 ? make_float2(ox - v[r].x, oy - v[r].y)
                   : make_float2(v[r].x + ox, v[r].y + oy);
    }
    #pragma unroll
    for (int s = 3; s >= 0; s--) {
        int m = 16 >> s;
        float2 wf = g_tw32[s*32 + lane];
        float2 w = make_float2(wf.x, -wf.y);
        bool up = (lane & m) != 0;
        #pragma unroll
        for (int r = 0; r < 10; r++) {
            float2 t = up ? cmul(v[r], w) : v[r];
            float ox = __shfl_xor_sync(0xffffffffu, t.x, m);
            float oy = __shfl_xor_sync(0xffffffffu, t.y, m);
            v[r] = up ? make_float2(ox - t.x, oy - t.y)
                      : make_float2(t.x + ox, t.y + oy);
        }
    }
    #pragma unroll
    for (int k = 1; k < 10; k++) {
        float2 wf = g_tw320[(k-1)*32 + lane];
        v[k] = cmul(v[k], make_float2(wf.x, -wf.y));
    }
    fft10<+1>(v);
}

// ---------------- block reduction (deterministic tree) ----------------
__device__ __forceinline__ float block_reduce_256(float v) {
    __shared__ float red[256];
    red[threadIdx.x] = v;
    __syncthreads();
    #pragma unroll
    for (int s = 128; s > 0; s >>= 1) {
        if (threadIdx.x < s) red[threadIdx.x] += red[threadIdx.x + s];
        __syncthreads();
    }
    return red[0];
}

// ---------------- twiddle table init (one-time per call, exact) ----------------
__global__ void __launch_bounds__(256) k_twinit() {
    int t = blockIdx.x * 256 + threadIdx.x;
    if (t < 288) {
        int k = t / 32 + 1, l = t & 31;
        double a = -2.0 * M_PI * (double)(k * l) / 320.0;
        double s, c; sincos(a, &s, &c);
        g_tw320[t] = make_float2((float)c, (float)s);
    } else if (t < 416) {
        int u = t - 288;
        int s2 = u >> 5, l = u & 31;
        int m = 16 >> s2;
        int j = l & (m - 1);
        double a = -M_PI * (double)j / (double)m;
        double ss, cc; sincos(a, &ss, &cc);
        g_tw32[u] = make_float2((float)cc, (float)ss);
    }
}

// ---------------- mask prep: permuted + scaled ----------------
__global__ void __launch_bounds__(256) k_maskprep(const int* __restrict__ mask) {
    int e = blockIdx.x * 256 + threadIdx.x;      // [0, B*HW)
    int b = e / HW; int rem = e - b * HW;
    int w_mem = rem / 320; int idx = rem - w_mem * 320;
    int l = idx & 31, j = idx >> 5;
    int hfreq = 10 * br5(l) + j;
    int wfreq = 10 * br5(w_mem & 31) + (w_mem >> 5);
    g_maskP[e] = (float)mask[b * HW + hfreq * 320 + wfreq] * (1.0f / 102400.0f);
}

// ---------------- K1: coil = csm*p ; forward row FFT (registers only) ----------------
__global__ void __launch_bounds__(256) k_rows_fwd(const float* __restrict__ csm) {
    int warp = threadIdx.x >> 5, lane = threadIdx.x & 31;
    int row = blockIdx.x * 8 + warp;          // bc*320 + h
    int bc = row / 320, h = row - bc * 320;
    int b = bc >> 4;
    const float2* crow = (const float2*)csm + bc * HW + h * WW;
    const float2* prow = g_p + b * HW + h * WW;
    float2 v[10];
    #pragma unroll
    for (int j = 0; j < 10; j++) {
        int idx = lane + 32 * j;
        v[j] = cmul(crow[idx], prow[idx]);
    }
    fft320_fwd(v, lane);
    float2* out = g_k + bc * HW + h * WW;
    #pragma unroll
    for (int j = 0; j < 10; j++) out[lane + 32 * j] = v[j];   // permuted-freq layout
}

// ---------------- K2: column FFT + mask + column IFFT ----------------
__global__ void __launch_bounds__(256) k_cols() {
    __shared__ float sRe[8][324];
    __shared__ float sIm[8][324];
    int bc = blockIdx.x / 40;
    int w0 = (blockIdx.x - bc * 40) * 8;
    int b = bc >> 4;
    float2* base = g_k + bc * HW;

    for (int idx = threadIdx.x; idx < 320 * 8; idx += 256) {
        int h = idx >> 3, c = idx & 7;
        float2 t = base[h * WW + w0 + c];
        sRe[c][h] = t.x; sIm[c][h] = t.y;
    }
    __syncthreads();

    int warp = threadIdx.x >> 5, lane = threadIdx.x & 31;
    float2 v[10];
    #pragma unroll
    for (int j = 0; j < 10; j++) {
        int h = lane + 32 * j;
        v[j] = make_float2(sRe[warp][h], sIm[warp][h]);
    }
    fft320_fwd(v, lane);

    const float* mrow = g_maskP + b * HW + (w0 + warp) * 320;
    #pragma unroll
    for (int j = 0; j < 10; j++) {
        float m = mrow[lane + 32 * j];
        v[j].x *= m; v[j].y *= m;
    }
    fft320_inv(v, lane);

    #pragma unroll
    for (int j = 0; j < 10; j++) {
        int h = lane + 32 * j;
        sRe[warp][h] = v[j].x; sIm[warp][h] = v[j].y;
    }
    __syncthreads();
    for (int idx = threadIdx.x; idx < 320 * 8; idx += 256) {
        int h = idx >> 3, c = idx & 7;
        base[h * WW + w0 + c] = make_float2(sRe[c][h], sIm[c][h]);
    }
}

// ---------------- K3: inverse row FFT + conj(csm) + combine + lam*p + p.Ap partial ----------------
__global__ void __launch_bounds__(256) k_inv_combine(const float* __restrict__ csm,
                                                     const float* __restrict__ lam) {
    __shared__ float2 sAcc[8][320];
    int warp = threadIdx.x >> 5, lane = threadIdx.x & 31;
    int b = blockIdx.x / 320, h = blockIdx.x - b * 320;

    float2 acc[10];
    #pragma unroll
    for (int j = 0; j < 10; j++) acc[j] = make_float2(0.f, 0.f);

    #pragma unroll
    for (int cc = 0; cc < 2; cc++) {
        int bc = b * 16 + warp + 8 * cc;
        const float2* krow = g_k + bc * HW + h * WW;
        float2 v[10];
        #pragma unroll
        for (int j = 0; j < 10; j++) v[j] = krow[lane + 32 * j];
        fft320_inv(v, lane);
        const float2* crow = (const float2*)csm + bc * HW + h * WW;
        #pragma unroll
        for (int j = 0; j < 10; j++) {
            float2 cv = crow[lane + 32 * j];
            float2 t = cmulconj(cv, v[j]);
            acc[j].x += t.x; acc[j].y += t.y;
        }
    }
    #pragma unroll
    for (int j = 0; j < 10; j++) sAcc[warp][lane + 32 * j] = acc[j];
    __syncthreads();

    const float2* prow = g_p + b * HW + h * WW;
    float2* aprow = g_Ap + b * HW + h * WW;
    float l0 = lam[0];
    float dot = 0.f;
    for (int e = threadIdx.x; e < 320; e += 256) {
        float2 s = make_float2(0.f, 0.f);
        #pragma unroll
        for (int w = 0; w < 8; w++) { s.x += sAcc[w][e].x; s.y += sAcc[w][e].y; }
        float2 pv = prow[e];
        float2 ap = make_float2(s.x + l0 * pv.x, s.y + l0 * pv.y);
        aprow[e] = ap;
        dot += pv.x * ap.x + pv.y * ap.y;
    }
    float tot = block_reduce_256(dot);
    if (threadIdx.x == 0) g_part[blockIdx.x] = tot;   // index = b*320 + h
}

// ---------------- alpha = rTr / pAp ----------------
__global__ void __launch_bounds__(256) k_alpha() {
    int b = blockIdx.x;
    float v = 0.f;
    for (int t = threadIdx.x; t < 320; t += 256) v += g_part[b * 320 + t];
    float tot = block_reduce_256(v);
    if (threadIdx.x == 0) g_alpha[b] = g_rTr[b] / tot;
}

// ---------------- x += a p ; r -= a Ap ; partial rTr_new ----------------
__global__ void __launch_bounds__(256) k_update_xr() {
    int b = blockIdx.x / RED_BLKS;
    int idx = (blockIdx.x - b * RED_BLKS) * 256 + threadIdx.x;
    int e = b * HW + idx;
    float a = g_alpha[b];
    float2 pv = g_p[e], ap = g_Ap[e];
    float2 xv = g_x[e];
    xv.x += a * pv.x; xv.y += a * pv.y;
    g_x[e] = xv;
    float2 rv = g_r[e];
    rv.x -= a * ap.x; rv.y -= a * ap.y;
    g_r[e] = rv;
    float rr = rv.x * rv.x + rv.y * rv.y;
    float tot = block_reduce_256(rr);
    if (threadIdx.x == 0) g_part[blockIdx.x] = tot;
}

// ---------------- beta = rTr_new / rTr ----------------
__global__ void __launch_bounds__(256) k_beta() {
    int b = blockIdx.x;
    float v = 0.f;
    for (int t = threadIdx.x; t < RED_BLKS; t += 256) v += g_part[b * RED_BLKS + t];
    float tot = block_reduce_256(v);
    if (threadIdx.x == 0) {
        g_beta[b] = tot / g_rTr[b];
        g_rTr[b] = tot;
    }
}

// ---------------- p = r + beta p ----------------
__global__ void __launch_bounds__(256) k_update_p() {
    int b = blockIdx.x / RED_BLKS;
    int idx = (blockIdx.x - b * RED_BLKS) * 256 + threadIdx.x;
    int e = b * HW + idx;
    float be = g_beta[b];
    float2 rv = g_r[e], pv = g_p[e];
    g_p[e] = make_float2(rv.x + be * pv.x, rv.y + be * pv.y);
}

// ---------------- init: p=r=rhs, x=0, rr partials ----------------
__global__ void __launch_bounds__(256) k_init(const float* __restrict__ rhs) {
    int b = blockIdx.x / RED_BLKS;
    int idx = (blockIdx.x - b * RED_BLKS) * 256 + threadIdx.x;
    int e = b * HW + idx;
    float re = rhs[(b * 2 + 0) * HW + idx];
    float im = rhs[(b * 2 + 1) * HW + idx];
    float2 v = make_float2(re, im);
    g_p[e] = v;
    g_r[e] = v;
    g_x[e] = make_float2(0.f, 0.f);
    float rr = re * re + im * im;
    float tot = block_reduce_256(rr);
    if (threadIdx.x == 0) g_part[blockIdx.x] = tot;
}

__global__ void __launch_bounds__(256) k_init_red() {
    int b = blockIdx.x;
    float v = 0.f;
    for (int t = threadIdx.x; t < RED_BLKS; t += 256) v += g_part[b * RED_BLKS + t];
    float tot = block_reduce_256(v);
    if (threadIdx.x == 0) g_rTr[b] = tot;
}

// ---------------- output: [B,H,W,2] ----------------
__global__ void __launch_bounds__(256) k_out(float* __restrict__ out) {
    int e = blockIdx.x * 256 + threadIdx.x;
    ((float2*)out)[e] = g_x[e];
}

// ---------------- launch ----------------
extern "C" void kernel_launch(void* const* d_in, const int* in_sizes, int n_in,
                              void* d_out, int out_size) {
    const float* rhs  = (const float*)d_in[0];
    const float* csm  = (const float*)d_in[1];
    const int*   mask = (const int*)d_in[2];
    const float* lam  = (const float*)d_in[3];
    float* out = (float*)d_out;

    const int EG = BATCH * RED_BLKS;      // 3200
    const int FG = BATCH * NC * HH / 8;   // 5120
    const int CG = BATCH * NC * (WW / 8); // 5120
    const int IG = BATCH * HH;            // 2560

    k_twinit<<<2, 256>>>();
    k_maskprep<<<EG, 256>>>(mask);
    k_init<<<EG, 256>>>(rhs);
    k_init_red<<<BATCH, 256>>>();

    for (int it = 0; it < NITER; it++) {
        k_rows_fwd<<<FG, 256>>>(csm);
        k_cols<<<CG, 256>>>();
        k_inv_combine<<<IG, 256>>>(csm, lam);
        k_alpha<<<BATCH, 256>>>();
        k_update_xr<<<EG, 256>>>();
        k_beta<<<BATCH, 256>>>();
        k_update_p<<<EG, 256>>>();
    }

    k_out<<<EG, 256>>>(out);
}